// round 5
// baseline (speedup 1.0000x reference)
#include <cuda_runtime.h>

#define T_FRAMES 60
#define HID 32
#define NG 128          // 4*HID gate rows
#define EPSF 1e-5f
#define FULLM 0xffffffffu

// scratch: per-frame input-side gate pre-activations.
// i/f/o rows pre-scaled by 0.5 (sigmoid-via-tanh); g rows unscaled.
__device__ float g_gx[T_FRAMES * NG];

__device__ __forceinline__ float tanha(float x) {
    float r; asm("tanh.approx.f32 %0, %1;" : "=f"(r) : "f"(x)); return r;
}

// ---------------------------------------------------------------------------
// Kernel 1: one block per frame (fully parallel across t).
//   f1 = relu(W00 x_t + b00); f2 = relu(W01 f1 + b01)
//   fn = LayerNorm(f2)*ln_g + ln_b
//   gx = W_ih fn + b_ih + b_hh   (i/f/o rows scaled by 0.5)
// ---------------------------------------------------------------------------
__global__ void frame_kernel(const float* __restrict__ x,
                             const float* __restrict__ w00, const float* __restrict__ b00,
                             const float* __restrict__ w01, const float* __restrict__ b01,
                             const float* __restrict__ lng, const float* __restrict__ lnb,
                             const float* __restrict__ wih, const float* __restrict__ bih,
                             const float* __restrict__ bhh)
{
    const int t = blockIdx.x;
    const int tid = threadIdx.x;

    __shared__ float sx[63];
    __shared__ float sf1[63];
    __shared__ float sf2[64];
    __shared__ float sfn[64];
    __shared__ float s_mu, s_rstd;

    if (tid < 63) sx[tid] = x[t * 63 + tid];
    __syncthreads();

    if (tid < 63) {
        float acc = b00[tid];
        const float* wr = w00 + tid * 63;
        #pragma unroll
        for (int k = 0; k < 63; k++) acc = fmaf(wr[k], sx[k], acc);
        sf1[tid] = fmaxf(acc, 0.0f);
    }
    __syncthreads();

    if (tid < 64) {
        float acc = b01[tid];
        const float* wr = w01 + tid * 63;
        #pragma unroll
        for (int k = 0; k < 63; k++) acc = fmaf(wr[k], sf1[k], acc);
        sf2[tid] = fmaxf(acc, 0.0f);
    }
    __syncthreads();

    if (tid < 32) {
        float v0 = sf2[tid], v1 = sf2[tid + 32];
        float s = v0 + v1;
        float q = v0 * v0 + v1 * v1;
        #pragma unroll
        for (int o = 16; o > 0; o >>= 1) {
            s += __shfl_xor_sync(FULLM, s, o);
            q += __shfl_xor_sync(FULLM, q, o);
        }
        if (tid == 0) {
            float mu  = s * (1.0f / 64.0f);
            float var = q * (1.0f / 64.0f) - mu * mu;
            s_mu   = mu;
            s_rstd = rsqrtf(var + EPSF);
        }
    }
    __syncthreads();

    if (tid < 64)
        sfn[tid] = (sf2[tid] - s_mu) * s_rstd * lng[tid] + lnb[tid];
    __syncthreads();

    {
        float acc = bih[tid] + bhh[tid];
        const float* wr = wih + tid * 64;
        #pragma unroll
        for (int k = 0; k < 64; k++) acc = fmaf(wr[k], sfn[k], acc);
        // g gate rows (64..95) unscaled; i/f/o rows scaled by 0.5
        float scale = ((tid >> 5) == 2) ? 1.0f : 0.5f;
        g_gx[t * NG + tid] = acc * scale;
    }
}

// ---------------------------------------------------------------------------
// Kernel 2: one block, ALL 4 warps drive the recurrence (one gate per warp):
//   warp 0 -> i, warp 1 -> f, warp 2 -> g, warp 3 -> o.
// Lane r of warp g holds W_hh row (32g + r) in 32 registers. Each warp
// computes its gate vector (32 SHFL + 32 FFMA), applies its activation,
// exchanges activated gates through double-buffered smem (ONE bar per step),
// then every warp redundantly updates c[lane], h[lane]. This divides the
// single-SMSP issue floor of the previous version by 4.
// ---------------------------------------------------------------------------
__global__ void __launch_bounds__(128, 1) seq_kernel(
    const float* __restrict__ whh,
    const float* __restrict__ bng, const float* __restrict__ bnb,
    const float* __restrict__ w10, const float* __restrict__ b10,
    const float* __restrict__ w11, const float* __restrict__ b11,
    const float* __restrict__ w12, const float* __restrict__ b12,
    float* __restrict__ out)
{
    __shared__ float sgx[T_FRAMES * NG];       // 30 KB
    __shared__ float sgate[2][NG];             // double-buffered gate exchange

    const int tid  = threadIdx.x;
    const int wid  = tid >> 5;
    const int lane = tid & 31;

    // cooperative preload of gx into smem (vectorized)
    {
        float4* s4 = reinterpret_cast<float4*>(sgx);
        const float4* g4 = reinterpret_cast<const float4*>(g_gx);
        #pragma unroll
        for (int i = tid; i < (T_FRAMES * NG) / 4; i += 128) s4[i] = g4[i];
    }

    // weights: lane holds W_hh row (wid*32 + lane), 32 columns in registers.
    // i/f/o warps pre-scale by 0.5 (sigmoid-via-tanh); g warp unscaled.
    const float wscale = (wid == 2) ? 1.0f : 0.5f;
    float w[HID];
    {
        const float4* wr = reinterpret_cast<const float4*>(whh + (wid * 32 + lane) * HID);
        #pragma unroll
        for (int k4 = 0; k4 < HID / 4; k4++) {
            float4 v = wr[k4];
            w[4 * k4 + 0] = v.x * wscale;
            w[4 * k4 + 1] = v.y * wscale;
            w[4 * k4 + 2] = v.z * wscale;
            w[4 * k4 + 3] = v.w * wscale;
        }
    }
    __syncthreads();

    float c, h;

    // ---- t = 0 peeled: h = 0 -> gate is just gx[0] ----
    {
        float g0 = sgx[wid * 32 + lane];
        float a  = (wid == 2) ? tanha(g0) : fmaf(0.5f, tanha(g0), 0.5f);
        sgate[0][wid * 32 + lane] = a;
        __syncthreads();
        float si = sgate[0][lane];
        float tg = sgate[0][64 + lane];
        float to = sgate[0][96 + lane];
        c = si * tg;                 // f-gate term vanishes (c0 = 0)
        h = to * tanha(c);
    }

    #pragma unroll 1
    for (int t = 1; t < T_FRAMES; t++) {
        float acc0 = sgx[t * NG + wid * 32 + lane];
        float acc1 = 0.0f, acc2 = 0.0f, acc3 = 0.0f;

        #pragma unroll
        for (int k = 0; k < HID; k += 4) {
            float h0 = __shfl_sync(FULLM, h, k);
            float h1 = __shfl_sync(FULLM, h, k + 1);
            float h2 = __shfl_sync(FULLM, h, k + 2);
            float h3 = __shfl_sync(FULLM, h, k + 3);
            acc0 = fmaf(w[k],     h0, acc0);
            acc1 = fmaf(w[k + 1], h1, acc1);
            acc2 = fmaf(w[k + 2], h2, acc2);
            acc3 = fmaf(w[k + 3], h3, acc3);
        }
        float g = (acc0 + acc1) + (acc2 + acc3);
        float a = (wid == 2) ? tanha(g) : fmaf(0.5f, tanha(g), 0.5f);

        float* buf = sgate[t & 1];
        buf[wid * 32 + lane] = a;
        __syncthreads();            // one barrier per step (double-buffered)

        float si = buf[lane];
        float sf = buf[32 + lane];
        float tg = buf[64 + lane];
        float to = buf[96 + lane];
        c = fmaf(sf, c, si * tg);   // every warp keeps its own copy of c
        h = to * tanha(c);          // ... and of h (identical across warps)
    }

    // ---- output head ----
    // All warps hold identical h[lane]; compute the two 32x32 layers
    // redundantly per warp (no syncs), split the final 256-row layer 4 ways.
    float hb = (h * rsqrtf(1.0f + EPSF)) * bng[lane] + bnb[lane];

    float o1 = b10[lane];
    #pragma unroll
    for (int k = 0; k < 32; k++)
        o1 = fmaf(w10[lane * 32 + k], __shfl_sync(FULLM, hb, k), o1);
    o1 = fmaxf(o1, 0.0f);

    float o2 = b11[lane];
    #pragma unroll
    for (int k = 0; k < 32; k++)
        o2 = fmaf(w11[lane * 32 + k], __shfl_sync(FULLM, o1, k), o2);
    o2 = fmaxf(o2, 0.0f);

    // warp g -> output rows [64g, 64g+64): 2 rows per lane
    const int r0 = wid * 64 + lane;
    const int r1 = r0 + 32;
    float a0 = b12[r0], a1 = b12[r1];
    #pragma unroll
    for (int k = 0; k < 32; k++) {
        float v = __shfl_sync(FULLM, o2, k);
        a0 = fmaf(w12[r0 * 32 + k], v, a0);
        a1 = fmaf(w12[r1 * 32 + k], v, a1);
    }
    out[r0] = a0;
    out[r1] = a1;
}

// ---------------------------------------------------------------------------
// Input order (metadata): x, w00, b00, w01, b01, ln_g, ln_b, w_ih, w_hh,
//                         b_ih, b_hh, bn_g, bn_b, w10, b10, w11, b11, w12, b12
// ---------------------------------------------------------------------------
extern "C" void kernel_launch(void* const* d_in, const int* in_sizes, int n_in,
                              void* d_out, int out_size)
{
    const float* x    = (const float*)d_in[0];
    const float* w00  = (const float*)d_in[1];
    const float* b00  = (const float*)d_in[2];
    const float* w01  = (const float*)d_in[3];
    const float* b01  = (const float*)d_in[4];
    const float* lng  = (const float*)d_in[5];
    const float* lnb  = (const float*)d_in[6];
    const float* wih  = (const float*)d_in[7];
    const float* whh  = (const float*)d_in[8];
    const float* bih  = (const float*)d_in[9];
    const float* bhh  = (const float*)d_in[10];
    const float* bng  = (const float*)d_in[11];
    const float* bnb  = (const float*)d_in[12];
    const float* w10  = (const float*)d_in[13];
    const float* b10  = (const float*)d_in[14];
    const float* w11  = (const float*)d_in[15];
    const float* b11  = (const float*)d_in[16];
    const float* w12  = (const float*)d_in[17];
    const float* b12  = (const float*)d_in[18];
    float* out = (float*)d_out;

    frame_kernel<<<T_FRAMES, 128>>>(x, w00, b00, w01, b01, lng, lnb, wih, bih, bhh);
    seq_kernel<<<1, 128>>>(whh, bng, bnb, w10, b10, w11, b11, w12, b12, out);
}

// round 6
// speedup vs baseline: 1.0484x; 1.0484x over previous
#include <cuda_runtime.h>

#define T_FRAMES 60
#define HID 32
#define NG 128          // 4*HID gate rows
#define EPSF 1e-5f
#define FULLM 0xffffffffu

// scratch: per-frame input-side gate pre-activations.
// i/f/o rows pre-scaled by 0.5 (sigmoid-via-tanh); g rows unscaled.
__device__ float g_gx[T_FRAMES * NG];

__device__ __forceinline__ float tanha(float x) {
    float r; asm("tanh.approx.f32 %0, %1;" : "=f"(r) : "f"(x)); return r;
}

// ---------------------------------------------------------------------------
// Kernel 1: one block per frame (fully parallel across t).
// ---------------------------------------------------------------------------
__global__ void frame_kernel(const float* __restrict__ x,
                             const float* __restrict__ w00, const float* __restrict__ b00,
                             const float* __restrict__ w01, const float* __restrict__ b01,
                             const float* __restrict__ lng, const float* __restrict__ lnb,
                             const float* __restrict__ wih, const float* __restrict__ bih,
                             const float* __restrict__ bhh)
{
    const int t = blockIdx.x;
    const int tid = threadIdx.x;

    __shared__ float sx[63];
    __shared__ float sf1[63];
    __shared__ float sf2[64];
    __shared__ float sfn[64];
    __shared__ float s_mu, s_rstd;

    if (tid < 63) sx[tid] = x[t * 63 + tid];
    __syncthreads();

    if (tid < 63) {
        float acc = b00[tid];
        const float* wr = w00 + tid * 63;
        #pragma unroll
        for (int k = 0; k < 63; k++) acc = fmaf(wr[k], sx[k], acc);
        sf1[tid] = fmaxf(acc, 0.0f);
    }
    __syncthreads();

    if (tid < 64) {
        float acc = b01[tid];
        const float* wr = w01 + tid * 63;
        #pragma unroll
        for (int k = 0; k < 63; k++) acc = fmaf(wr[k], sf1[k], acc);
        sf2[tid] = fmaxf(acc, 0.0f);
    }
    __syncthreads();

    if (tid < 32) {
        float v0 = sf2[tid], v1 = sf2[tid + 32];
        float s = v0 + v1;
        float q = v0 * v0 + v1 * v1;
        #pragma unroll
        for (int o = 16; o > 0; o >>= 1) {
            s += __shfl_xor_sync(FULLM, s, o);
            q += __shfl_xor_sync(FULLM, q, o);
        }
        if (tid == 0) {
            float mu  = s * (1.0f / 64.0f);
            float var = q * (1.0f / 64.0f) - mu * mu;
            s_mu   = mu;
            s_rstd = rsqrtf(var + EPSF);
        }
    }
    __syncthreads();

    if (tid < 64)
        sfn[tid] = (sf2[tid] - s_mu) * s_rstd * lng[tid] + lnb[tid];
    __syncthreads();

    {
        float acc = bih[tid] + bhh[tid];
        const float* wr = wih + tid * 64;
        #pragma unroll
        for (int k = 0; k < 64; k++) acc = fmaf(wr[k], sfn[k], acc);
        // g gate rows (64..95) unscaled; i/f/o rows scaled by 0.5
        float scale = ((tid >> 5) == 2) ? 1.0f : 0.5f;
        g_gx[t * NG + tid] = acc * scale;
    }
}

// ---------------------------------------------------------------------------
// Kernel 2: one block, 4 warps, one gate per warp (w0=i, w1=f, w2=g, w3=o).
// ZERO shuffles in the recurrence:
//   - h broadcast: each warp keeps a PRIVATE smem copy of h (written
//     redundantly, read via LDS.128 broadcast after __syncwarp only).
//   - gate exchange: transposed buffer sgate[j*4+gate] -> each lane reads
//     all 4 activated gates with ONE LDS.128 after the single __syncthreads.
// ---------------------------------------------------------------------------
__global__ void __launch_bounds__(128, 1) seq_kernel(
    const float* __restrict__ whh,
    const float* __restrict__ bng, const float* __restrict__ bnb,
    const float* __restrict__ w10, const float* __restrict__ b10,
    const float* __restrict__ w11, const float* __restrict__ b11,
    const float* __restrict__ w12, const float* __restrict__ b12,
    float* __restrict__ out)
{
    __shared__ float sgx[T_FRAMES * NG];              // 30 KB
    __shared__ __align__(16) float sgate[2][NG];      // [j*4 + gate], double-buffered
    __shared__ __align__(16) float shbuf[4][HID];     // per-warp private h copy

    const int tid  = threadIdx.x;
    const int wid  = tid >> 5;
    const int lane = tid & 31;

    // cooperative preload of gx into smem (vectorized)
    {
        float4* s4 = reinterpret_cast<float4*>(sgx);
        const float4* g4 = reinterpret_cast<const float4*>(g_gx);
        #pragma unroll
        for (int i = tid; i < (T_FRAMES * NG) / 4; i += 128) s4[i] = g4[i];
    }

    // weights: lane holds W_hh row (wid*32 + lane), 32 columns in registers.
    // i/f/o warps pre-scale by 0.5 (sigmoid-via-tanh); g warp unscaled.
    const float wscale = (wid == 2) ? 1.0f : 0.5f;
    float w[HID];
    {
        const float4* wr = reinterpret_cast<const float4*>(whh + (wid * 32 + lane) * HID);
        #pragma unroll
        for (int k4 = 0; k4 < HID / 4; k4++) {
            float4 v = wr[k4];
            w[4 * k4 + 0] = v.x * wscale;
            w[4 * k4 + 1] = v.y * wscale;
            w[4 * k4 + 2] = v.z * wscale;
            w[4 * k4 + 3] = v.w * wscale;
        }
    }
    __syncthreads();

    float c, h;

    // ---- t = 0 peeled: h = 0 -> gate is just gx[0] ----
    {
        float g0 = sgx[wid * 32 + lane];
        float a  = tanha(g0);
        if (wid != 2) a = fmaf(0.5f, a, 0.5f);
        sgate[0][lane * 4 + wid] = a;
        __syncthreads();
        float4 gv = *reinterpret_cast<const float4*>(&sgate[0][lane * 4]); // (i,f,g,o)
        c = gv.x * gv.z;                  // f-gate term vanishes (c0 = 0)
        h = gv.w * tanha(c);
    }

    #pragma unroll 1
    for (int t = 1; t < T_FRAMES; t++) {
        // publish h to this warp's private buffer (no cross-warp traffic)
        shbuf[wid][lane] = h;
        float gx0 = sgx[t * NG + wid * 32 + lane];
        __syncwarp();

        float acc[8];
        acc[0] = gx0;
        #pragma unroll
        for (int i = 1; i < 8; i++) acc[i] = 0.0f;

        #pragma unroll
        for (int k4 = 0; k4 < 8; k4++) {
            float4 hv = *reinterpret_cast<const float4*>(&shbuf[wid][k4 * 4]); // broadcast
            acc[k4] = fmaf(w[4 * k4 + 0], hv.x, acc[k4]);
            acc[k4] = fmaf(w[4 * k4 + 1], hv.y, acc[k4]);
            acc[k4] = fmaf(w[4 * k4 + 2], hv.z, acc[k4]);
            acc[k4] = fmaf(w[4 * k4 + 3], hv.w, acc[k4]);
        }
        float g = ((acc[0] + acc[1]) + (acc[2] + acc[3]))
                + ((acc[4] + acc[5]) + (acc[6] + acc[7]));

        float a = tanha(g);
        if (wid != 2) a = fmaf(0.5f, a, 0.5f);

        float* buf = sgate[t & 1];
        buf[lane * 4 + wid] = a;          // transposed write
        __syncthreads();                  // one barrier per step

        float4 gv = *reinterpret_cast<const float4*>(&buf[lane * 4]); // (i,f,g,o)
        c = fmaf(gv.y, c, gv.x * gv.z);   // every warp keeps its own c
        h = gv.w * tanha(c);              // ... and h (identical across warps)
    }

    // ---- output head ----
    // All warps hold identical h[lane]; two 32x32 layers redundant per warp,
    // final 256-row layer split across warps.
    float hb = (h * rsqrtf(1.0f + EPSF)) * bng[lane] + bnb[lane];

    float o1 = b10[lane];
    #pragma unroll
    for (int k = 0; k < 32; k++)
        o1 = fmaf(w10[lane * 32 + k], __shfl_sync(FULLM, hb, k), o1);
    o1 = fmaxf(o1, 0.0f);

    float o2 = b11[lane];
    #pragma unroll
    for (int k = 0; k < 32; k++)
        o2 = fmaf(w11[lane * 32 + k], __shfl_sync(FULLM, o1, k), o2);
    o2 = fmaxf(o2, 0.0f);

    // warp g -> output rows [64g, 64g+64): 2 rows per lane
    const int r0 = wid * 64 + lane;
    const int r1 = r0 + 32;
    float a0 = b12[r0], a1 = b12[r1];
    #pragma unroll
    for (int k = 0; k < 32; k++) {
        float v = __shfl_sync(FULLM, o2, k);
        a0 = fmaf(w12[r0 * 32 + k], v, a0);
        a1 = fmaf(w12[r1 * 32 + k], v, a1);
    }
    out[r0] = a0;
    out[r1] = a1;
}

// ---------------------------------------------------------------------------
// Input order (metadata): x, w00, b00, w01, b01, ln_g, ln_b, w_ih, w_hh,
//                         b_ih, b_hh, bn_g, bn_b, w10, b10, w11, b11, w12, b12
// ---------------------------------------------------------------------------
extern "C" void kernel_launch(void* const* d_in, const int* in_sizes, int n_in,
                              void* d_out, int out_size)
{
    const float* x    = (const float*)d_in[0];
    const float* w00  = (const float*)d_in[1];
    const float* b00  = (const float*)d_in[2];
    const float* w01  = (const float*)d_in[3];
    const float* b01  = (const float*)d_in[4];
    const float* lng  = (const float*)d_in[5];
    const float* lnb  = (const float*)d_in[6];
    const float* wih  = (const float*)d_in[7];
    const float* whh  = (const float*)d_in[8];
    const float* bih  = (const float*)d_in[9];
    const float* bhh  = (const float*)d_in[10];
    const float* bng  = (const float*)d_in[11];
    const float* bnb  = (const float*)d_in[12];
    const float* w10  = (const float*)d_in[13];
    const float* b10  = (const float*)d_in[14];
    const float* w11  = (const float*)d_in[15];
    const float* b11  = (const float*)d_in[16];
    const float* w12  = (const float*)d_in[17];
    const float* b12  = (const float*)d_in[18];
    float* out = (float*)d_out;

    frame_kernel<<<T_FRAMES, 128>>>(x, w00, b00, w01, b01, lng, lnb, wih, bih, bhh);
    seq_kernel<<<1, 128>>>(whh, bng, bnb, w10, b10, w11, b11, w12, b12, out);
}